// round 10
// baseline (speedup 1.0000x reference)
#include <cuda_runtime.h>

// Pure HBM-streaming quadratic form:
//   total = sum over pairs (l1<=l2), weight w in {1,2}:
//           w * sum_s d1[s,:] . O[s,:,:] . d2[s,:],   d = c_in - c_tgt
// Overlap tensors: 356.5 MB read once -> memory-bound (~6.3 TB/s measured).
// R10 = R3 streaming schedule (21760 one-unit blocks, IT=4, 8 CTAs/SM,
//       linear per-block 16KB sweeps) but SINGLE kernel:
//       d computed inline from c_in/c_tgt (__ldg, L1-hits; no prep node,
//       no g_d, no staging, no syncthreads before streaming),
//       output via last-block finalize (validated in R4).

#define TPB 256
#define IT  4                 // float4 per thread; unit = TPB*IT*4 = 4096 floats
#define NUNITS 21760

__device__ float    g_acc;    // zero-init at load; drained+reset by last block
__device__ unsigned g_cnt;    // zero-init at load; reset by last block

struct Ptrs {
    const float4* o[10];      // ovlp pairs (0,0)(0,1)(0,2)(0,3)(1,1)(1,2)(1,3)(2,2)(2,3)(3,3)
    const float*  cin[4];     // c_in_l0..l3  (flattened [S, D_l])
    const float*  ctg[4];     // c_tgt_l0..l3
};

// One unit of one pair; identical index math / stream order to R3.
// d1, d2 computed inline from the tiny coefficient arrays (L1-resident).
template <int D1, int D2, int W>
__device__ __forceinline__ float unit_acc(const float4* __restrict__ o,
                                          const float* __restrict__ in1,
                                          const float* __restrict__ tg1,
                                          const float4* __restrict__ in2,
                                          const float4* __restrict__ tg2,
                                          int lu, int tid) {
    constexpr unsigned C4 = D2 / 4;   // float4 columns; >= 64 so a warp shares one row r
    float acc = 0.0f;
    unsigned base = (unsigned)lu * (TPB * IT) + tid;
#pragma unroll
    for (int it = 0; it < IT; ++it) {
        unsigned idx4 = base + (unsigned)it * TPB;
        unsigned c4 = idx4 % C4;
        unsigned rs = idx4 / C4;
        unsigned r  = rs % (unsigned)D1;
        unsigned s  = rs / (unsigned)D1;
        float4 ov = __ldcs(&o[idx4]);                       // streamed, evict-first
        unsigned ci = s * C4 + c4;                          // d2 float4 index
        float4 a2 = __ldg(in2 + ci);                        // L1-resident
        float4 b2 = __ldg(tg2 + ci);
        unsigned si = s * D1 + r;                           // d1 scalar index
        float d1 = __ldg(in1 + si) - __ldg(tg1 + si);       // warp-uniform
        float dot = ov.x * (a2.x - b2.x) + ov.y * (a2.y - b2.y)
                  + ov.z * (a2.z - b2.z) + ov.w * (a2.w - b2.w);
        acc = fmaf(d1, dot, acc);
    }
    return (W == 2) ? (acc + acc) : acc;   // weight once per block
}

// Unit-count prefix sums (unit = 4096 floats), same as R3:
// (0,0):128 (0,1):512 (0,2):1152 (0,3):2048 (1,1):3200
// (1,2):5120 (1,3):7808 (2,2):11008 (2,3):15488 (3,3):21760
__global__ void __launch_bounds__(TPB, 8) rho_kernel(Ptrs P, float* __restrict__ out) {
    const int b = blockIdx.x;
    const int tid = threadIdx.x;
    float acc;
    if      (b <   128) acc = unit_acc< 256,  256, 1>(P.o[0], P.cin[0], P.ctg[0], (const float4*)P.cin[0], (const float4*)P.ctg[0], b,         tid);
    else if (b <   512) acc = unit_acc< 256,  768, 2>(P.o[1], P.cin[0], P.ctg[0], (const float4*)P.cin[1], (const float4*)P.ctg[1], b -   128, tid);
    else if (b <  1152) acc = unit_acc< 256, 1280, 2>(P.o[2], P.cin[0], P.ctg[0], (const float4*)P.cin[2], (const float4*)P.ctg[2], b -   512, tid);
    else if (b <  2048) acc = unit_acc< 256, 1792, 2>(P.o[3], P.cin[0], P.ctg[0], (const float4*)P.cin[3], (const float4*)P.ctg[3], b -  1152, tid);
    else if (b <  3200) acc = unit_acc< 768,  768, 1>(P.o[4], P.cin[1], P.ctg[1], (const float4*)P.cin[1], (const float4*)P.ctg[1], b -  2048, tid);
    else if (b <  5120) acc = unit_acc< 768, 1280, 2>(P.o[5], P.cin[1], P.ctg[1], (const float4*)P.cin[2], (const float4*)P.ctg[2], b -  3200, tid);
    else if (b <  7808) acc = unit_acc< 768, 1792, 2>(P.o[6], P.cin[1], P.ctg[1], (const float4*)P.cin[3], (const float4*)P.ctg[3], b -  5120, tid);
    else if (b < 11008) acc = unit_acc<1280, 1280, 1>(P.o[7], P.cin[2], P.ctg[2], (const float4*)P.cin[2], (const float4*)P.ctg[2], b -  7808, tid);
    else if (b < 15488) acc = unit_acc<1280, 1792, 2>(P.o[8], P.cin[2], P.ctg[2], (const float4*)P.cin[3], (const float4*)P.ctg[3], b - 11008, tid);
    else                acc = unit_acc<1792, 1792, 1>(P.o[9], P.cin[3], P.ctg[3], (const float4*)P.cin[3], (const float4*)P.ctg[3], b - 15488, tid);

    // warp reduce
#pragma unroll
    for (int off = 16; off > 0; off >>= 1)
        acc += __shfl_down_sync(0xffffffffu, acc, off);

    __shared__ float ws[TPB / 32];
    if ((tid & 31) == 0) ws[tid >> 5] = acc;
    __syncthreads();
    if (tid == 0) {
        float s = ws[0];
#pragma unroll
        for (int w = 1; w < TPB / 32; ++w) s += ws[w];
        atomicAdd(&g_acc, s);
        __threadfence();
        unsigned old = atomicAdd(&g_cnt, 1u);
        if (old == NUNITS - 1) {
            float v = atomicExch(&g_acc, 0.0f);   // drain + reset for next replay
            out[0] = v;
            atomicExch(&g_cnt, 0u);               // reset counter for next replay
        }
    }
}

extern "C" void kernel_launch(void* const* d_in, const int* in_sizes, int n_in,
                              void* d_out, int out_size) {
    (void)in_sizes; (void)n_in; (void)out_size;
    Ptrs P;
    // inputs: c_in_l0, c_tgt_l0, ..., c_in_l3, c_tgt_l3, then 10 ovlp blocks
    for (int l = 0; l < 4; ++l) {
        P.cin[l] = (const float*)d_in[2 * l];
        P.ctg[l] = (const float*)d_in[2 * l + 1];
    }
    for (int k = 0; k < 10; ++k) P.o[k] = (const float4*)d_in[8 + k];

    rho_kernel<<<NUNITS, TPB>>>(P, (float*)d_out);
}

// round 11
// speedup vs baseline: 1.3056x; 1.3056x over previous
#include <cuda_runtime.h>

// Pure HBM-streaming quadratic form:
//   total = sum over pairs (l1<=l2), weight w in {1,2}:
//           w * sum_s d1[s,:] . O[s,:,:] . d2[s,:],   d = c_in - c_tgt
// Overlap tensors: 356.5 MB read once -> memory-bound (~6.3 TB/s plateau).
// R11 = R3 schedule exactly (21760 one-unit blocks, 4096-float linear units,
//       prep kernel + g_d, 8 CTAs/SM) but with Blackwell 256-bit loads
//       (ld.global.v8.f32): half the LDGs, half the index ALU, 1KB contiguous
//       per warp-iter. Stream byte order unchanged.

#define TPB 256
#define IT  2                 // float8 (32B) per thread per iter; unit = 256*2*8 = 4096 floats
#define NUNITS 21760

// delta coefficients, concatenated by l:
//   l0: [0,2048), l1: [2048,8192), l2: [8192,18432), l3: [18432,32768)
__device__ __align__(32) float g_d[32768];

__global__ void prep_kernel(const float* __restrict__ i0, const float* __restrict__ t0,
                            const float* __restrict__ i1, const float* __restrict__ t1,
                            const float* __restrict__ i2, const float* __restrict__ t2,
                            const float* __restrict__ i3, const float* __restrict__ t3,
                            float* out) {
    int idx = blockIdx.x * blockDim.x + threadIdx.x;
    if (idx == 0) out[0] = 0.0f;
    if (idx < 2048) {
        g_d[idx] = i0[idx] - t0[idx];
    } else if (idx < 8192) {
        int j = idx - 2048;  g_d[idx] = i1[j] - t1[j];
    } else if (idx < 18432) {
        int j = idx - 8192;  g_d[idx] = i2[j] - t2[j];
    } else if (idx < 32768) {
        int j = idx - 18432; g_d[idx] = i3[j] - t3[j];
    }
}

struct OvlpPtrs { const float* p[10]; };

// 256-bit streamed load (evict-first) — sm_100+/sm_103a LDG.E.256
__device__ __forceinline__ void ldg256_cs(const float* p, float v[8]) {
    asm volatile("ld.global.cs.v8.f32 {%0,%1,%2,%3,%4,%5,%6,%7}, [%8];"
                 : "=f"(v[0]), "=f"(v[1]), "=f"(v[2]), "=f"(v[3]),
                   "=f"(v[4]), "=f"(v[5]), "=f"(v[6]), "=f"(v[7])
                 : "l"(p));
}
// 256-bit read-only cached load (L1-resident d2)
__device__ __forceinline__ void ldg256_nc(const float* p, float v[8]) {
    asm volatile("ld.global.nc.v8.f32 {%0,%1,%2,%3,%4,%5,%6,%7}, [%8];"
                 : "=f"(v[0]), "=f"(v[1]), "=f"(v[2]), "=f"(v[3]),
                   "=f"(v[4]), "=f"(v[5]), "=f"(v[6]), "=f"(v[7])
                 : "l"(p));
}

// One unit of one pair; same linear float order as R3, 32B granules.
// lu = local unit index within this pair's range. Weight applied once.
template <int D1, int D2, int W, int OFF1, int OFF2>
__device__ __forceinline__ float unit_acc(const float* __restrict__ o, int lu, int tid) {
    constexpr unsigned C8 = D2 / 8;   // float8 columns per row; multiple of 32
    float acc = 0.0f;
    unsigned base = (unsigned)lu * (TPB * IT) + tid;   // in float8 units
#pragma unroll
    for (int it = 0; it < IT; ++it) {
        unsigned idx8 = base + (unsigned)it * TPB;
        unsigned c8 = idx8 % C8;                  // compile-time divisor -> mul-shift
        unsigned rs = idx8 / C8;
        unsigned r  = rs % (unsigned)D1;
        unsigned s  = rs / (unsigned)D1;
        float ov[8], d2[8];
        ldg256_cs(o + idx8 * 8, ov);                       // streamed, evict-first
        ldg256_nc(g_d + OFF2 + s * D2 + c8 * 8, d2);       // L1-resident
        float d1 = __ldg(&g_d[OFF1 + s * D1 + r]);         // warp-uniform broadcast
        float dot = ov[0] * d2[0];
        dot = fmaf(ov[1], d2[1], dot);
        dot = fmaf(ov[2], d2[2], dot);
        dot = fmaf(ov[3], d2[3], dot);
        dot = fmaf(ov[4], d2[4], dot);
        dot = fmaf(ov[5], d2[5], dot);
        dot = fmaf(ov[6], d2[6], dot);
        dot = fmaf(ov[7], d2[7], dot);
        acc = fmaf(d1, dot, acc);
    }
    return (W == 2) ? (acc + acc) : acc;   // weight once per block
}

// Unit-count prefix sums (unit = 4096 floats), identical to R3:
// (0,0):128 (0,1):512 (0,2):1152 (0,3):2048 (1,1):3200
// (1,2):5120 (1,3):7808 (2,2):11008 (2,3):15488 (3,3):21760
__global__ void __launch_bounds__(TPB, 8) rho_kernel(OvlpPtrs o, float* __restrict__ out) {
    int b = blockIdx.x;
    int tid = threadIdx.x;
    float acc;
    if      (b <   128) acc = unit_acc< 256,  256, 1,     0,     0>(o.p[0], b,         tid);
    else if (b <   512) acc = unit_acc< 256,  768, 2,     0,  2048>(o.p[1], b -   128, tid);
    else if (b <  1152) acc = unit_acc< 256, 1280, 2,     0,  8192>(o.p[2], b -   512, tid);
    else if (b <  2048) acc = unit_acc< 256, 1792, 2,     0, 18432>(o.p[3], b -  1152, tid);
    else if (b <  3200) acc = unit_acc< 768,  768, 1,  2048,  2048>(o.p[4], b -  2048, tid);
    else if (b <  5120) acc = unit_acc< 768, 1280, 2,  2048,  8192>(o.p[5], b -  3200, tid);
    else if (b <  7808) acc = unit_acc< 768, 1792, 2,  2048, 18432>(o.p[6], b -  5120, tid);
    else if (b < 11008) acc = unit_acc<1280, 1280, 1,  8192,  8192>(o.p[7], b -  7808, tid);
    else if (b < 15488) acc = unit_acc<1280, 1792, 2,  8192, 18432>(o.p[8], b - 11008, tid);
    else                acc = unit_acc<1792, 1792, 1, 18432, 18432>(o.p[9], b - 15488, tid);

    // warp reduce
#pragma unroll
    for (int off = 16; off > 0; off >>= 1)
        acc += __shfl_down_sync(0xffffffffu, acc, off);

    __shared__ float ws[TPB / 32];
    if ((tid & 31) == 0) ws[tid >> 5] = acc;
    __syncthreads();
    if (tid == 0) {
        float s = ws[0];
#pragma unroll
        for (int w = 1; w < TPB / 32; ++w) s += ws[w];
        atomicAdd(out, s);
    }
}

extern "C" void kernel_launch(void* const* d_in, const int* in_sizes, int n_in,
                              void* d_out, int out_size) {
    (void)in_sizes; (void)n_in; (void)out_size;
    const float* i0 = (const float*)d_in[0];
    const float* t0 = (const float*)d_in[1];
    const float* i1 = (const float*)d_in[2];
    const float* t1 = (const float*)d_in[3];
    const float* i2 = (const float*)d_in[4];
    const float* t2 = (const float*)d_in[5];
    const float* i3 = (const float*)d_in[6];
    const float* t3 = (const float*)d_in[7];

    OvlpPtrs o;
    for (int k = 0; k < 10; ++k) o.p[k] = (const float*)d_in[8 + k];

    float* out = (float*)d_out;
    prep_kernel<<<128, TPB>>>(i0, t0, i1, t1, i2, t2, i3, t3, out);
    rho_kernel<<<NUNITS, TPB>>>(o, out);
}

// round 12
// speedup vs baseline: 1.3250x; 1.0148x over previous
#include <cuda_runtime.h>

// Pure HBM-streaming quadratic form:
//   total = sum over pairs (l1<=l2), weight w in {1,2}:
//           w * sum_s d1[s,:] . O[s,:,:] . d2[s,:],   d = c_in - c_tgt
// Overlap tensors: 356.5 MB read once -> memory-bound.
// R12 = R11 rho kernel unchanged (256-bit loads, 6.68 TB/s, 54 us)
//       + PDL: rho launched with ProgrammaticStreamSerialization and
//       griddepcontrol.wait at entry -> rho's launch ramp overlaps prep,
//       removing the ~2.9 us inter-node serialization gap.

#define TPB 256
#define IT  2                 // float8 (32B) per thread per iter; unit = 256*2*8 = 4096 floats
#define NUNITS 21760

// delta coefficients, concatenated by l:
//   l0: [0,2048), l1: [2048,8192), l2: [8192,18432), l3: [18432,32768)
__device__ __align__(32) float g_d[32768];

__global__ void prep_kernel(const float* __restrict__ i0, const float* __restrict__ t0,
                            const float* __restrict__ i1, const float* __restrict__ t1,
                            const float* __restrict__ i2, const float* __restrict__ t2,
                            const float* __restrict__ i3, const float* __restrict__ t3,
                            float* out) {
    int idx = blockIdx.x * blockDim.x + threadIdx.x;
    if (idx == 0) out[0] = 0.0f;
    if (idx < 2048) {
        g_d[idx] = i0[idx] - t0[idx];
    } else if (idx < 8192) {
        int j = idx - 2048;  g_d[idx] = i1[j] - t1[j];
    } else if (idx < 18432) {
        int j = idx - 8192;  g_d[idx] = i2[j] - t2[j];
    } else if (idx < 32768) {
        int j = idx - 18432; g_d[idx] = i3[j] - t3[j];
    }
}

struct OvlpPtrs { const float* p[10]; };

// 256-bit streamed load (evict-first) — sm_103a LDG.E.256
__device__ __forceinline__ void ldg256_cs(const float* p, float v[8]) {
    asm volatile("ld.global.cs.v8.f32 {%0,%1,%2,%3,%4,%5,%6,%7}, [%8];"
                 : "=f"(v[0]), "=f"(v[1]), "=f"(v[2]), "=f"(v[3]),
                   "=f"(v[4]), "=f"(v[5]), "=f"(v[6]), "=f"(v[7])
                 : "l"(p));
}
// 256-bit read-only cached load (L1-resident d2)
__device__ __forceinline__ void ldg256_nc(const float* p, float v[8]) {
    asm volatile("ld.global.nc.v8.f32 {%0,%1,%2,%3,%4,%5,%6,%7}, [%8];"
                 : "=f"(v[0]), "=f"(v[1]), "=f"(v[2]), "=f"(v[3]),
                   "=f"(v[4]), "=f"(v[5]), "=f"(v[6]), "=f"(v[7])
                 : "l"(p));
}

// One unit of one pair; linear float order, 32B granules.
template <int D1, int D2, int W, int OFF1, int OFF2>
__device__ __forceinline__ float unit_acc(const float* __restrict__ o, int lu, int tid) {
    constexpr unsigned C8 = D2 / 8;   // float8 columns per row; multiple of 32
    float acc = 0.0f;
    unsigned base = (unsigned)lu * (TPB * IT) + tid;   // in float8 units
#pragma unroll
    for (int it = 0; it < IT; ++it) {
        unsigned idx8 = base + (unsigned)it * TPB;
        unsigned c8 = idx8 % C8;                  // compile-time divisor -> mul-shift
        unsigned rs = idx8 / C8;
        unsigned r  = rs % (unsigned)D1;
        unsigned s  = rs / (unsigned)D1;
        float ov[8], d2[8];
        ldg256_cs(o + idx8 * 8, ov);                       // streamed, evict-first
        ldg256_nc(g_d + OFF2 + s * D2 + c8 * 8, d2);       // L1-resident
        float d1 = __ldg(&g_d[OFF1 + s * D1 + r]);         // warp-uniform broadcast
        float dot = ov[0] * d2[0];
        dot = fmaf(ov[1], d2[1], dot);
        dot = fmaf(ov[2], d2[2], dot);
        dot = fmaf(ov[3], d2[3], dot);
        dot = fmaf(ov[4], d2[4], dot);
        dot = fmaf(ov[5], d2[5], dot);
        dot = fmaf(ov[6], d2[6], dot);
        dot = fmaf(ov[7], d2[7], dot);
        acc = fmaf(d1, dot, acc);
    }
    return (W == 2) ? (acc + acc) : acc;   // weight once per block
}

// Unit-count prefix sums (unit = 4096 floats):
// (0,0):128 (0,1):512 (0,2):1152 (0,3):2048 (1,1):3200
// (1,2):5120 (1,3):7808 (2,2):11008 (2,3):15488 (3,3):21760
__global__ void __launch_bounds__(TPB, 8) rho_kernel(OvlpPtrs o, float* __restrict__ out) {
    // PDL: blocks may launch while prep_kernel is still running. Wait for the
    // upstream grid (implicit trigger at its completion -> g_d/out visible).
    asm volatile("griddepcontrol.wait;" ::: "memory");

    int b = blockIdx.x;
    int tid = threadIdx.x;
    float acc;
    if      (b <   128) acc = unit_acc< 256,  256, 1,     0,     0>(o.p[0], b,         tid);
    else if (b <   512) acc = unit_acc< 256,  768, 2,     0,  2048>(o.p[1], b -   128, tid);
    else if (b <  1152) acc = unit_acc< 256, 1280, 2,     0,  8192>(o.p[2], b -   512, tid);
    else if (b <  2048) acc = unit_acc< 256, 1792, 2,     0, 18432>(o.p[3], b -  1152, tid);
    else if (b <  3200) acc = unit_acc< 768,  768, 1,  2048,  2048>(o.p[4], b -  2048, tid);
    else if (b <  5120) acc = unit_acc< 768, 1280, 2,  2048,  8192>(o.p[5], b -  3200, tid);
    else if (b <  7808) acc = unit_acc< 768, 1792, 2,  2048, 18432>(o.p[6], b -  5120, tid);
    else if (b < 11008) acc = unit_acc<1280, 1280, 1,  8192,  8192>(o.p[7], b -  7808, tid);
    else if (b < 15488) acc = unit_acc<1280, 1792, 2,  8192, 18432>(o.p[8], b - 11008, tid);
    else                acc = unit_acc<1792, 1792, 1, 18432, 18432>(o.p[9], b - 15488, tid);

    // warp reduce
#pragma unroll
    for (int off = 16; off > 0; off >>= 1)
        acc += __shfl_down_sync(0xffffffffu, acc, off);

    __shared__ float ws[TPB / 32];
    if ((tid & 31) == 0) ws[tid >> 5] = acc;
    __syncthreads();
    if (tid == 0) {
        float s = ws[0];
#pragma unroll
        for (int w = 1; w < TPB / 32; ++w) s += ws[w];
        atomicAdd(out, s);
    }
}

extern "C" void kernel_launch(void* const* d_in, const int* in_sizes, int n_in,
                              void* d_out, int out_size) {
    (void)in_sizes; (void)n_in; (void)out_size;
    const float* i0 = (const float*)d_in[0];
    const float* t0 = (const float*)d_in[1];
    const float* i1 = (const float*)d_in[2];
    const float* t1 = (const float*)d_in[3];
    const float* i2 = (const float*)d_in[4];
    const float* t2 = (const float*)d_in[5];
    const float* i3 = (const float*)d_in[6];
    const float* t3 = (const float*)d_in[7];

    OvlpPtrs o;
    for (int k = 0; k < 10; ++k) o.p[k] = (const float*)d_in[8 + k];

    float* out = (float*)d_out;
    prep_kernel<<<128, TPB>>>(i0, t0, i1, t1, i2, t2, i3, t3, out);

    // PDL launch: rho may begin launching while prep executes; griddepcontrol.wait
    // inside rho enforces the dependency with full memory visibility.
    cudaLaunchConfig_t cfg = {};
    cfg.gridDim = dim3(NUNITS);
    cfg.blockDim = dim3(TPB);
    cfg.dynamicSmemBytes = 0;
    cfg.stream = 0;
    cudaLaunchAttribute attrs[1];
    attrs[0].id = cudaLaunchAttributeProgrammaticStreamSerialization;
    attrs[0].val.programmaticStreamSerializationAllowed = 1;
    cfg.attrs = attrs;
    cfg.numAttrs = 1;
    cudaLaunchKernelEx(&cfg, rho_kernel, o, out);
}